// round 6
// baseline (speedup 1.0000x reference)
#include <cuda_runtime.h>
#include <cuda_fp16.h>
#include <mma.h>
#include <stdint.h>

using namespace nvcuda;

// Problem constants
constexpr int B  = 2;
constexpr int SQ = 2048;
constexpr int SK = 2048;
constexpr int D  = 1024;
constexpr int NH = 16;
constexpr int H  = 64;
constexpr int M  = B * SQ;
constexpr float EPS = 1e-5f;

// ---------------- device scratch (static, no allocation) ----------------
// hi/lo fp16 split buffers for every MMA operand
__device__ __align__(16) __half g_xq_hi [M * D];
__device__ __align__(16) __half g_xq_lo [M * D];
__device__ __align__(16) __half g_xkv_hi[M * D];
__device__ __align__(16) __half g_xkv_lo[M * D];
__device__ __align__(16) __half g_Wq_hi [D * D];
__device__ __align__(16) __half g_Wq_lo [D * D];
__device__ __align__(16) __half g_Wk_hi [D * D];
__device__ __align__(16) __half g_Wk_lo [D * D];
__device__ __align__(16) __half g_Wv_hi [D * D];
__device__ __align__(16) __half g_Wv_lo [D * D];
__device__ __align__(16) __half g_Wo_hi [D * D];
__device__ __align__(16) __half g_Wo_lo [D * D];
__device__ __align__(16) float  g_qf [M * D];
__device__ __align__(16) float  g_kf [M * D];
__device__ __align__(16) float  g_vf [M * D];
__device__ __align__(16) __half g_qh_hi[M * D];
__device__ __align__(16) __half g_qh_lo[M * D];
__device__ __align__(16) __half g_kh_hi[M * D];
__device__ __align__(16) __half g_kh_lo[M * D];
__device__ __align__(16) __half g_vh_hi[M * D];
__device__ __align__(16) __half g_vh_lo[M * D];
__device__ __align__(16) __half g_zh_hi[M * D];
__device__ __align__(16) __half g_zh_lo[M * D];

__device__ __forceinline__ void split2(float x, __half& hi, __half& lo) {
    __half h = __float2half(x);
    hi = h;
    lo = __float2half(x - __half2float(h));
}

// ---------------- conversion kernels ----------------
__global__ void k_convert_x(const float* __restrict__ xq, const float* __restrict__ xkv) {
    int i = blockIdx.x * blockDim.x + threadIdx.x;
    if (i < M * D) {
        split2(xq [i], g_xq_hi [i], g_xq_lo [i]);
        split2(xkv[i], g_xkv_hi[i], g_xkv_lo[i]);
    }
}

__global__ void k_convert_w(const float* __restrict__ WQ, const float* __restrict__ WK,
                            const float* __restrict__ WV, const float* __restrict__ WO) {
    int i = blockIdx.x * blockDim.x + threadIdx.x;
    if (i < D * D) {
        int d   = i >> 10;
        int col = i & 1023;
        int n   = col >> 6;
        int h   = col & 63;
        int src = n * D * H + d * H + h;   // W[n][d][h] -> [D, N*H]
        split2(WQ[src], g_Wq_hi[i], g_Wq_lo[i]);
        split2(WK[src], g_Wk_hi[i], g_Wk_lo[i]);
        split2(WV[src], g_Wv_hi[i], g_Wv_lo[i]);
        split2(WO[i],   g_Wo_hi[i], g_Wo_lo[i]);  // [N,H,D] flat == [N*H,D]
    }
}

// ---------------- split-fp16 wmma GEMM: C = A*B + bias (fp32-accurate) ----------------
// SEL: 0 xq*Wq->qf | 1 xkv*Wk->kf | 2 xkv*Wv->vf | 3 zh*Wo->Cext
constexpr int BT = 64;

template <int SEL>
__global__ void k_gemm(const float* __restrict__ bias, float* __restrict__ Cext) {
    const __half* A_hi = (SEL == 0) ? g_xq_hi : (SEL == 3) ? g_zh_hi : g_xkv_hi;
    const __half* A_lo = (SEL == 0) ? g_xq_lo : (SEL == 3) ? g_zh_lo : g_xkv_lo;
    const __half* B_hi = (SEL == 0) ? g_Wq_hi : (SEL == 1) ? g_Wk_hi : (SEL == 2) ? g_Wv_hi : g_Wo_hi;
    const __half* B_lo = (SEL == 0) ? g_Wq_lo : (SEL == 1) ? g_Wk_lo : (SEL == 2) ? g_Wv_lo : g_Wo_lo;
    float*        Cf   = (SEL == 0) ? g_qf   : (SEL == 1) ? g_kf   : (SEL == 2) ? g_vf   : Cext;

    // 36,864 B static: As_hi | As_lo | Bs_hi | Bs_lo (each 64x72 half = 9216 B).
    // Cs (64x72 float = 18,432 B) aliases As region after the k-loop.
    __shared__ __align__(16) char sraw[36864];
    __half (*As_hi)[72] = reinterpret_cast<__half(*)[72]>(sraw);
    __half (*As_lo)[72] = reinterpret_cast<__half(*)[72]>(sraw + 9216);
    __half (*Bs_hi)[72] = reinterpret_cast<__half(*)[72]>(sraw + 18432);
    __half (*Bs_lo)[72] = reinterpret_cast<__half(*)[72]>(sraw + 27648);
    float  (*Cs)[72]    = reinterpret_cast<float (*)[72]>(sraw);

    const int tid  = threadIdx.x;
    const int warp = tid >> 5;
    const int row0 = blockIdx.y * BT;
    const int col0 = blockIdx.x * BT;

    wmma::fragment<wmma::accumulator, 16, 16, 16, float> acc[4];
#pragma unroll
    for (int i = 0; i < 4; i++) wmma::fill_fragment(acc[i], 0.0f);

    for (int k0 = 0; k0 < D; k0 += BT) {
#pragma unroll
        for (int it = 0; it < 4; it++) {
            int idx = tid + it * 128;
            int r   = idx >> 3;
            int c8  = (idx & 7) * 8;
            size_t ai = (size_t)(row0 + r) * D + k0   + c8;
            size_t bi = (size_t)(k0   + r) * D + col0 + c8;
            *(uint4*)&As_hi[r][c8] = *(const uint4*)&A_hi[ai];
            *(uint4*)&As_lo[r][c8] = *(const uint4*)&A_lo[ai];
            *(uint4*)&Bs_hi[r][c8] = *(const uint4*)&B_hi[bi];
            *(uint4*)&Bs_lo[r][c8] = *(const uint4*)&B_lo[bi];
        }
        __syncthreads();
#pragma unroll
        for (int ks = 0; ks < 4; ks++) {
            wmma::fragment<wmma::matrix_a, 16, 16, 16, __half, wmma::row_major> ahi, alo;
            wmma::load_matrix_sync(ahi, &As_hi[warp * 16][ks * 16], 72);
            wmma::load_matrix_sync(alo, &As_lo[warp * 16][ks * 16], 72);
#pragma unroll
            for (int nf = 0; nf < 4; nf++) {
                wmma::fragment<wmma::matrix_b, 16, 16, 16, __half, wmma::row_major> bf;
                wmma::load_matrix_sync(bf, &Bs_hi[ks * 16][nf * 16], 72);
                wmma::mma_sync(acc[nf], ahi, bf, acc[nf]);
                wmma::mma_sync(acc[nf], alo, bf, acc[nf]);
                wmma::load_matrix_sync(bf, &Bs_lo[ks * 16][nf * 16], 72);
                wmma::mma_sync(acc[nf], ahi, bf, acc[nf]);
            }
        }
        __syncthreads();
    }
#pragma unroll
    for (int nf = 0; nf < 4; nf++)
        wmma::store_matrix_sync(&Cs[warp * 16][nf * 16], acc[nf], 72, wmma::mem_row_major);
    __syncthreads();

    for (int idx = tid; idx < BT * BT; idx += 128) {
        int r = idx >> 6, c = idx & 63;
        Cf[(size_t)(row0 + r) * D + col0 + c] = Cs[r][c] + bias[col0 + c];
    }
}

// ---------------- per-head LayerNorm over H=64 ----------------
// SEL: 0 = q (g_qf -> g_qh_*), 1 = k (g_kf -> g_kh_*, + fp32 out)
template <int SEL>
__global__ void k_ln(const float* __restrict__ g, const float* __restrict__ bb,
                     float* __restrict__ out_f) {
    const float* in     = (SEL == 0) ? g_qf    : g_kf;
    __half*      out_hi = (SEL == 0) ? g_qh_hi : g_kh_hi;
    __half*      out_lo = (SEL == 0) ? g_qh_lo : g_kh_lo;

    int row  = blockIdx.x * 8 + (threadIdx.x >> 5);
    int lane = threadIdx.x & 31;
    const float* p = in + (size_t)row * H;
    float v0 = p[lane], v1 = p[lane + 32];
    float s = v0 + v1;
#pragma unroll
    for (int o = 16; o; o >>= 1) s += __shfl_xor_sync(0xffffffffu, s, o);
    float mean = s * (1.0f / 64.0f);
    float d0 = v0 - mean, d1 = v1 - mean;
    float q = d0 * d0 + d1 * d1;
#pragma unroll
    for (int o = 16; o; o >>= 1) q += __shfl_xor_sync(0xffffffffu, q, o);
    float rstd = rsqrtf(q * (1.0f / 64.0f) + EPS);
    float o0 = d0 * rstd * g[lane]      + bb[lane];
    float o1 = d1 * rstd * g[lane + 32] + bb[lane + 32];
    size_t base = (size_t)row * H;
    split2(o0, out_hi[base + lane],      out_lo[base + lane]);
    split2(o1, out_hi[base + lane + 32], out_lo[base + lane + 32]);
    if (out_f) {
        out_f[base + lane]      = o0;
        out_f[base + lane + 32] = o1;
    }
}

// ---------------- v: fp32 -> hi/lo halves + copy to output ----------------
__global__ void k_vcast(float* __restrict__ out_f) {
    int i = blockIdx.x * blockDim.x + threadIdx.x;
    if (i < M * D) {
        float v = g_vf[i];
        split2(v, g_vh_hi[i], g_vh_lo[i]);
        if (out_f) out_f[i] = v;
    }
}

// ---------------- flash attention (split-fp16, fp32-accurate) ----------------
// Q-tile 32, KV-tile 64, 128 threads. Dynamic smem = 73,984 B.
constexpr int ATT_SMEM = 73984;

__global__ void k_attn() {
    extern __shared__ __align__(16) char sm[];
    __half (*Qhi)[72] = reinterpret_cast<__half(*)[72]>(sm);            // 4608
    __half (*Qlo)[72] = reinterpret_cast<__half(*)[72]>(sm + 4608);     // 4608
    __half (*Khi)[72] = reinterpret_cast<__half(*)[72]>(sm + 9216);     // 9216
    __half (*Klo)[72] = reinterpret_cast<__half(*)[72]>(sm + 18432);    // 9216
    __half (*Vhi)[72] = reinterpret_cast<__half(*)[72]>(sm + 27648);    // 9216
    __half (*Vlo)[72] = reinterpret_cast<__half(*)[72]>(sm + 36864);    // 9216
    float  (*Ss )[72] = reinterpret_cast<float (*)[72]>(sm + 46080);    // 9216
    __half (*Phi)[72] = reinterpret_cast<__half(*)[72]>(sm + 55296);    // 4608
    __half (*Plo)[72] = reinterpret_cast<__half(*)[72]>(sm + 59904);    // 4608
    float  (*Zs )[72] = reinterpret_cast<float (*)[72]>(sm + 64512);    // 9216
    float* ms = reinterpret_cast<float*>(sm + 73728);                   // 128
    float* ls = reinterpret_cast<float*>(sm + 73856);                   // 128

    const int qt = blockIdx.x, n = blockIdx.y, b = blockIdx.z;
    const int tid = threadIdx.x, warp = tid >> 5;
    const int qbase = qt * 32;
    const int r0  = (warp & 1) * 16;
    const int c0w = (warp >> 1) * 32;

    // load Q tile (hi+lo): 32x64
#pragma unroll
    for (int it = 0; it < 2; it++) {
        int idx = tid + it * 128;
        int r = idx >> 3, c8 = (idx & 7) * 8;
        size_t gi = (((size_t)b * SQ + qbase + r) * NH + n) * H + c8;
        *(uint4*)&Qhi[r][c8] = *(const uint4*)&g_qh_hi[gi];
        *(uint4*)&Qlo[r][c8] = *(const uint4*)&g_qh_lo[gi];
    }
    for (int idx = tid; idx < 32 * 72; idx += 128) (&Zs[0][0])[idx] = 0.0f;
    if (tid < 32) { ms[tid] = -1e30f; ls[tid] = 0.0f; }
    __syncthreads();

    const int jmax = (qbase + 31) >> 6;
    for (int j = 0; j <= jmax; j++) {
        const int kbase = j * 64;
#pragma unroll
        for (int it = 0; it < 4; it++) {
            int idx = tid + it * 128;
            int r = idx >> 3, c8 = (idx & 7) * 8;
            size_t gi = (((size_t)b * SK + kbase + r) * NH + n) * H + c8;
            *(uint4*)&Khi[r][c8] = *(const uint4*)&g_kh_hi[gi];
            *(uint4*)&Klo[r][c8] = *(const uint4*)&g_kh_lo[gi];
            *(uint4*)&Vhi[r][c8] = *(const uint4*)&g_vh_hi[gi];
            *(uint4*)&Vlo[r][c8] = *(const uint4*)&g_vh_lo[gi];
        }
        __syncthreads();

        // S = Q @ K^T  (hi*hi + lo*hi + hi*lo)
        wmma::fragment<wmma::accumulator, 16, 16, 16, float> sacc[2];
#pragma unroll
        for (int nf = 0; nf < 2; nf++) wmma::fill_fragment(sacc[nf], 0.0f);
#pragma unroll
        for (int ks = 0; ks < 4; ks++) {
            wmma::fragment<wmma::matrix_a, 16, 16, 16, __half, wmma::row_major> qhi, qlo;
            wmma::load_matrix_sync(qhi, &Qhi[r0][ks * 16], 72);
            wmma::load_matrix_sync(qlo, &Qlo[r0][ks * 16], 72);
#pragma unroll
            for (int nf = 0; nf < 2; nf++) {
                wmma::fragment<wmma::matrix_b, 16, 16, 16, __half, wmma::col_major> bf;
                wmma::load_matrix_sync(bf, &Khi[c0w + nf * 16][ks * 16], 72);
                wmma::mma_sync(sacc[nf], qhi, bf, sacc[nf]);
                wmma::mma_sync(sacc[nf], qlo, bf, sacc[nf]);
                wmma::load_matrix_sync(bf, &Klo[c0w + nf * 16][ks * 16], 72);
                wmma::mma_sync(sacc[nf], qhi, bf, sacc[nf]);
            }
        }
#pragma unroll
        for (int nf = 0; nf < 2; nf++)
            wmma::store_matrix_sync(&Ss[r0][c0w + nf * 16], sacc[nf], 72, wmma::mem_row_major);
        __syncthreads();

        // online softmax: 4 threads per row, 16 cols each
        {
            const int row = tid >> 2;
            const int c0  = (tid & 3) * 16;
            const int qidx = qbase + row;
            float vals[16];
            float mx = -1e30f;
#pragma unroll
            for (int c = 0; c < 16; c++) {
                int kidx = kbase + c0 + c;
                float s = (kidx <= qidx) ? Ss[row][c0 + c] : -1e30f;
                vals[c] = s;
                mx = fmaxf(mx, s);
            }
            mx = fmaxf(mx, __shfl_xor_sync(0xffffffffu, mx, 1));
            mx = fmaxf(mx, __shfl_xor_sync(0xffffffffu, mx, 2));
            float mold = ms[row];
            float mnew = fmaxf(mold, mx);
            float sum = 0.0f;
#pragma unroll
            for (int c = 0; c < 16; c++) {
                float p = (vals[c] > -1e29f) ? __expf(vals[c] - mnew) : 0.0f;
                split2(p, Phi[row][c0 + c], Plo[row][c0 + c]);
                sum += p;
            }
            sum += __shfl_xor_sync(0xffffffffu, sum, 1);
            sum += __shfl_xor_sync(0xffffffffu, sum, 2);
            float alpha = __expf(mold - mnew);
            if ((tid & 3) == 0) {
                ms[row] = mnew;
                ls[row] = ls[row] * alpha + sum;
            }
#pragma unroll
            for (int c = 0; c < 16; c++) Zs[row][c0 + c] *= alpha;
        }
        __syncthreads();

        // Z += P @ V  (hi*hi + lo*hi + hi*lo)
        wmma::fragment<wmma::accumulator, 16, 16, 16, float> zacc[2];
#pragma unroll
        for (int nf = 0; nf < 2; nf++)
            wmma::load_matrix_sync(zacc[nf], &Zs[r0][c0w + nf * 16], 72, wmma::mem_row_major);
#pragma unroll
        for (int ks = 0; ks < 4; ks++) {
            wmma::fragment<wmma::matrix_a, 16, 16, 16, __half, wmma::row_major> phi, plo;
            wmma::load_matrix_sync(phi, &Phi[r0][ks * 16], 72);
            wmma::load_matrix_sync(plo, &Plo[r0][ks * 16], 72);
#pragma unroll
            for (int nf = 0; nf < 2; nf++) {
                wmma::fragment<wmma::matrix_b, 16, 16, 16, __half, wmma::row_major> bf;
                wmma::load_matrix_sync(bf, &Vhi[ks * 16][c0w + nf * 16], 72);
                wmma::mma_sync(zacc[nf], phi, bf, zacc[nf]);
                wmma::mma_sync(zacc[nf], plo, bf, zacc[nf]);
                wmma::load_matrix_sync(bf, &Vlo[ks * 16][c0w + nf * 16], 72);
                wmma::mma_sync(zacc[nf], phi, bf, zacc[nf]);
            }
        }
#pragma unroll
        for (int nf = 0; nf < 2; nf++)
            wmma::store_matrix_sync(&Zs[r0][c0w + nf * 16], zacc[nf], 72, wmma::mem_row_major);
        __syncthreads();
    }

    // finalize: z = Z / l  (split into hi/lo for the O GEMM)
    {
        const int row = tid >> 2;
        const int c0  = (tid & 3) * 16;
        float inv = 1.0f / ls[row];
#pragma unroll
        for (int c = 0; c < 16; c++) {
            float z = Zs[row][c0 + c] * inv;
            size_t gi = (((size_t)b * SQ + qbase + row) * NH + n) * H + c0 + c;
            split2(z, g_zh_hi[gi], g_zh_lo[gi]);
        }
    }
}

// ---------------- launch ----------------
extern "C" void kernel_launch(void* const* d_in, const int* in_sizes, int n_in,
                              void* d_out, int out_size) {
    const float* x_q   = (const float*)d_in[0];
    const float* x_kv  = (const float*)d_in[1];
    // d_in[2] = mask (causal, recomputed analytically)
    const float* W_Q   = (const float*)d_in[3];
    const float* W_K   = (const float*)d_in[4];
    const float* W_V   = (const float*)d_in[5];
    const float* W_O   = (const float*)d_in[6];
    const float* b_Q   = (const float*)d_in[7];
    const float* b_K   = (const float*)d_in[8];
    const float* b_V   = (const float*)d_in[9];
    const float* b_O   = (const float*)d_in[10];
    const float* ln1_g = (const float*)d_in[11];
    const float* ln1_b = (const float*)d_in[12];
    const float* ln2_g = (const float*)d_in[13];
    const float* ln2_b = (const float*)d_in[14];

    float* out_f = (float*)d_out;
    float* k_out = nullptr;
    float* v_out = nullptr;
    if (out_size >= 3 * M * D) {
        k_out = out_f + (size_t)M * D;
        v_out = out_f + (size_t)2 * M * D;
    }

    cudaFuncSetAttribute(k_attn, cudaFuncAttributeMaxDynamicSharedMemorySize, ATT_SMEM);

    const int TPB = 256;
    k_convert_x<<<(M * D + TPB - 1) / TPB, TPB>>>(x_q, x_kv);
    k_convert_w<<<(D * D + TPB - 1) / TPB, TPB>>>(W_Q, W_K, W_V, W_O);

    dim3 ggrid(D / BT, M / BT);   // (16, 64)
    k_gemm<0><<<ggrid, 128>>>(b_Q, nullptr);
    k_gemm<1><<<ggrid, 128>>>(b_K, nullptr);
    k_gemm<2><<<ggrid, 128>>>(b_V, nullptr);

    k_ln<0><<<(M * NH) / 8, 256>>>(ln1_g, ln1_b, nullptr);
    k_ln<1><<<(M * NH) / 8, 256>>>(ln2_g, ln2_b, k_out);
    k_vcast<<<(M * D + TPB - 1) / TPB, TPB>>>(v_out);

    dim3 agrid(SQ / 32, NH, B);   // (64, 16, 2)
    k_attn<<<agrid, 128, ATT_SMEM>>>();

    k_gemm<3><<<ggrid, 128>>>(b_O, out_f);
}

// round 7
// speedup vs baseline: 1.3025x; 1.3025x over previous
#include <cuda_runtime.h>
#include <cuda_fp16.h>
#include <mma.h>
#include <stdint.h>

using namespace nvcuda;

// Problem constants
constexpr int B  = 2;
constexpr int SQ = 2048;
constexpr int SK = 2048;
constexpr int D  = 1024;
constexpr int NH = 16;
constexpr int H  = 64;
constexpr int M  = B * SQ;
constexpr float EPS = 1e-5f;

// ---------------- device scratch ----------------
__device__ __align__(16) __half g_xq_hi [M * D];
__device__ __align__(16) __half g_xq_lo [M * D];
__device__ __align__(16) __half g_xkv_hi[M * D];
__device__ __align__(16) __half g_xkv_lo[M * D];
__device__ __align__(16) __half g_Wq_hi [D * D];
__device__ __align__(16) __half g_Wq_lo [D * D];
__device__ __align__(16) __half g_Wk_hi [D * D];
__device__ __align__(16) __half g_Wk_lo [D * D];
__device__ __align__(16) __half g_Wv_hi [D * D];
__device__ __align__(16) __half g_Wv_lo [D * D];
__device__ __align__(16) __half g_Wo_hi [D * D];
__device__ __align__(16) __half g_Wo_lo [D * D];
__device__ __align__(16) float  g_qf [M * D];
__device__ __align__(16) float  g_kf [M * D];
__device__ __align__(16) __half g_qh_hi[M * D];
__device__ __align__(16) __half g_qh_lo[M * D];
__device__ __align__(16) __half g_kh_hi[M * D];
__device__ __align__(16) __half g_kh_lo[M * D];
__device__ __align__(16) __half g_vh_hi[M * D];
__device__ __align__(16) __half g_vh_lo[M * D];
__device__ __align__(16) __half g_zh_hi[M * D];
__device__ __align__(16) __half g_zh_lo[M * D];

__device__ __forceinline__ void split2(float x, __half& hi, __half& lo) {
    __half h = __float2half(x);
    hi = h;
    lo = __float2half(x - __half2float(h));
}

__device__ __forceinline__ void cp16(void* dst, const void* src) {
    uint32_t d = (uint32_t)__cvta_generic_to_shared(dst);
    asm volatile("cp.async.cg.shared.global [%0], [%1], 16;\n" :: "r"(d), "l"(src));
}
__device__ __forceinline__ void cp_commit() { asm volatile("cp.async.commit_group;\n"); }
template <int N>
__device__ __forceinline__ void cp_wait() { asm volatile("cp.async.wait_group %0;\n" :: "n"(N)); }

// ---------------- conversion kernels ----------------
__global__ void k_convert_x(const float* __restrict__ xq, const float* __restrict__ xkv) {
    int i = blockIdx.x * blockDim.x + threadIdx.x;
    if (i < M * D) {
        split2(xq [i], g_xq_hi [i], g_xq_lo [i]);
        split2(xkv[i], g_xkv_hi[i], g_xkv_lo[i]);
    }
}

__global__ void k_convert_w(const float* __restrict__ WQ, const float* __restrict__ WK,
                            const float* __restrict__ WV, const float* __restrict__ WO) {
    int i = blockIdx.x * blockDim.x + threadIdx.x;
    if (i < D * D) {
        int d   = i >> 10;
        int col = i & 1023;
        int n   = col >> 6;
        int h   = col & 63;
        int src = n * D * H + d * H + h;   // W[n][d][h] -> [D, N*H]
        split2(WQ[src], g_Wq_hi[i], g_Wq_lo[i]);
        split2(WK[src], g_Wk_hi[i], g_Wk_lo[i]);
        split2(WV[src], g_Wv_hi[i], g_Wv_lo[i]);
        split2(WO[i],   g_Wo_hi[i], g_Wo_lo[i]);  // [N,H,D] flat == [N*H,D]
    }
}

// ---------------- pipelined split-fp16 GEMM: 128x128x32, 256 threads ----------------
// SEL: 0 xq*Wq->qf | 1 xkv*Wk->kf | 2 xkv*Wv->vh(hi/lo)+Cext | 3 zh*Wo->Cext
constexpr int BM = 128, BN = 128, BK = 32;
constexpr int A_LD = 40;    // halfs per row (32 + 8 pad)
constexpr int B_LD = 136;   // halfs per row (128 + 8 pad)
constexpr int A_BYTES = BM * A_LD * 2;              // 10240
constexpr int B_BYTES = BK * B_LD * 2;              // 8704
constexpr int STAGE_BYTES = 2 * A_BYTES + 2 * B_BYTES;  // 37888 (Ahi,Alo,Bhi,Blo)
constexpr int GEMM_SMEM = 2 * STAGE_BYTES;          // 75776; Cs(128*132*4=67584) aliases
constexpr int C_LD = 132;

template <int SEL>
__global__ __launch_bounds__(256) void k_gemm(const float* __restrict__ bias,
                                              float* __restrict__ Cext) {
    const __half* A_hi = (SEL == 0) ? g_xq_hi : (SEL == 3) ? g_zh_hi : g_xkv_hi;
    const __half* A_lo = (SEL == 0) ? g_xq_lo : (SEL == 3) ? g_zh_lo : g_xkv_lo;
    const __half* B_hi = (SEL == 0) ? g_Wq_hi : (SEL == 1) ? g_Wk_hi : (SEL == 2) ? g_Wv_hi : g_Wo_hi;
    const __half* B_lo = (SEL == 0) ? g_Wq_lo : (SEL == 1) ? g_Wk_lo : (SEL == 2) ? g_Wv_lo : g_Wo_lo;

    extern __shared__ __align__(16) char smem[];

    const int tid    = threadIdx.x;
    const int warp   = tid >> 5;
    const int warp_m = warp >> 2;       // 0..1  -> 64 rows
    const int warp_n = warp & 3;        // 0..3  -> 32 cols
    const int row0   = blockIdx.y * BM;
    const int col0   = blockIdx.x * BN;

    auto load_stage = [&](int s, int k0) {
        char* st = smem + s * STAGE_BYTES;
        __half* sAh = (__half*)st;
        __half* sAl = (__half*)(st + A_BYTES);
        __half* sBh = (__half*)(st + 2 * A_BYTES);
        __half* sBl = (__half*)(st + 2 * A_BYTES + B_BYTES);
#pragma unroll
        for (int t = 0; t < 2; t++) {
            int idx = tid + t * 256;                 // 0..511
            int ar = idx >> 2, ac = (idx & 3) * 8;   // A: 128 rows x 32 cols
            size_t ai = (size_t)(row0 + ar) * D + k0 + ac;
            cp16(&sAh[ar * A_LD + ac], &A_hi[ai]);
            cp16(&sAl[ar * A_LD + ac], &A_lo[ai]);
            int br = idx >> 4, bc = (idx & 15) * 8;  // B: 32 rows x 128 cols
            size_t bi = (size_t)(k0 + br) * D + col0 + bc;
            cp16(&sBh[br * B_LD + bc], &B_hi[bi]);
            cp16(&sBl[br * B_LD + bc], &B_lo[bi]);
        }
        cp_commit();
    };

    wmma::fragment<wmma::accumulator, 16, 16, 16, float> acc[4][2];
#pragma unroll
    for (int i = 0; i < 4; i++)
#pragma unroll
        for (int j = 0; j < 2; j++) wmma::fill_fragment(acc[i][j], 0.0f);

    constexpr int NIT = D / BK;   // 32
    load_stage(0, 0);

    for (int it = 0; it < NIT; it++) {
        if (it + 1 < NIT) {
            load_stage((it + 1) & 1, (it + 1) * BK);
            cp_wait<1>();
        } else {
            cp_wait<0>();
        }
        __syncthreads();

        char* st = smem + (it & 1) * STAGE_BYTES;
        __half* sAh = (__half*)st;
        __half* sAl = (__half*)(st + A_BYTES);
        __half* sBh = (__half*)(st + 2 * A_BYTES);
        __half* sBl = (__half*)(st + 2 * A_BYTES + B_BYTES);

#pragma unroll
        for (int kf = 0; kf < 2; kf++) {
            wmma::fragment<wmma::matrix_a, 16, 16, 16, __half, wmma::row_major> ahi[4], alo[4];
#pragma unroll
            for (int mi = 0; mi < 4; mi++) {
                int r = warp_m * 64 + mi * 16;
                wmma::load_matrix_sync(ahi[mi], &sAh[r * A_LD + kf * 16], A_LD);
                wmma::load_matrix_sync(alo[mi], &sAl[r * A_LD + kf * 16], A_LD);
            }
#pragma unroll
            for (int ni = 0; ni < 2; ni++) {
                int c = warp_n * 32 + ni * 16;
                wmma::fragment<wmma::matrix_b, 16, 16, 16, __half, wmma::row_major> bhi, blo;
                wmma::load_matrix_sync(bhi, &sBh[kf * 16 * B_LD + c], B_LD);
                wmma::load_matrix_sync(blo, &sBl[kf * 16 * B_LD + c], B_LD);
#pragma unroll
                for (int mi = 0; mi < 4; mi++) {
                    wmma::mma_sync(acc[mi][ni], ahi[mi], bhi, acc[mi][ni]);
                    wmma::mma_sync(acc[mi][ni], alo[mi], bhi, acc[mi][ni]);
                    wmma::mma_sync(acc[mi][ni], ahi[mi], blo, acc[mi][ni]);
                }
            }
        }
        __syncthreads();
    }

    // epilogue through smem (aliases stage buffers; synced above)
    float* Cs = (float*)smem;
#pragma unroll
    for (int mi = 0; mi < 4; mi++)
#pragma unroll
        for (int ni = 0; ni < 2; ni++)
            wmma::store_matrix_sync(&Cs[(warp_m * 64 + mi * 16) * C_LD + warp_n * 32 + ni * 16],
                                    acc[mi][ni], C_LD, wmma::mem_row_major);
    __syncthreads();

    for (int idx = tid; idx < BM * BN; idx += 256) {
        int r = idx >> 7, c = idx & 127;
        float val = Cs[r * C_LD + c] + bias[col0 + c];
        size_t gi = (size_t)(row0 + r) * D + col0 + c;
        if (SEL == 0)      g_qf[gi] = val;
        else if (SEL == 1) g_kf[gi] = val;
        else if (SEL == 2) {
            split2(val, g_vh_hi[gi], g_vh_lo[gi]);
            if (Cext) Cext[gi] = val;
        } else {
            Cext[gi] = val;
        }
    }
}

// ---------------- per-head LayerNorm over H=64 ----------------
template <int SEL>
__global__ void k_ln(const float* __restrict__ g, const float* __restrict__ bb,
                     float* __restrict__ out_f) {
    const float* in     = (SEL == 0) ? g_qf    : g_kf;
    __half*      out_hi = (SEL == 0) ? g_qh_hi : g_kh_hi;
    __half*      out_lo = (SEL == 0) ? g_qh_lo : g_kh_lo;

    int row  = blockIdx.x * 8 + (threadIdx.x >> 5);
    int lane = threadIdx.x & 31;
    const float* p = in + (size_t)row * H;
    float v0 = p[lane], v1 = p[lane + 32];
    float s = v0 + v1;
#pragma unroll
    for (int o = 16; o; o >>= 1) s += __shfl_xor_sync(0xffffffffu, s, o);
    float mean = s * (1.0f / 64.0f);
    float d0 = v0 - mean, d1 = v1 - mean;
    float q = d0 * d0 + d1 * d1;
#pragma unroll
    for (int o = 16; o; o >>= 1) q += __shfl_xor_sync(0xffffffffu, q, o);
    float rstd = rsqrtf(q * (1.0f / 64.0f) + EPS);
    float o0 = d0 * rstd * g[lane]      + bb[lane];
    float o1 = d1 * rstd * g[lane + 32] + bb[lane + 32];
    size_t base = (size_t)row * H;
    split2(o0, out_hi[base + lane],      out_lo[base + lane]);
    split2(o1, out_hi[base + lane + 32], out_lo[base + lane + 32]);
    if (out_f) {
        out_f[base + lane]      = o0;
        out_f[base + lane + 32] = o1;
    }
}

// ---------------- flash attention: Q-tile 64, KV-tile 64, 256 threads ----------------
// dynamic smem layout (bytes):
constexpr int ATT_QHI = 0;           // 64x72 half = 9216
constexpr int ATT_QLO = 9216;
constexpr int ATT_KHI = 18432;
constexpr int ATT_KLO = 27648;
constexpr int ATT_VHI = 36864;
constexpr int ATT_VLO = 46080;
constexpr int ATT_SS  = 55296;       // 64x72 float = 18432
constexpr int ATT_PHI = 73728;
constexpr int ATT_PLO = 82944;
constexpr int ATT_ZS  = 92160;       // 18432
constexpr int ATT_MS  = 110592;      // 256
constexpr int ATT_LS  = 110848;      // 256
constexpr int ATT_SMEM = 111104;

__global__ __launch_bounds__(256) void k_attn() {
    extern __shared__ __align__(16) char sm[];
    __half (*Qhi)[72] = reinterpret_cast<__half(*)[72]>(sm + ATT_QHI);
    __half (*Qlo)[72] = reinterpret_cast<__half(*)[72]>(sm + ATT_QLO);
    __half (*Khi)[72] = reinterpret_cast<__half(*)[72]>(sm + ATT_KHI);
    __half (*Klo)[72] = reinterpret_cast<__half(*)[72]>(sm + ATT_KLO);
    __half (*Vhi)[72] = reinterpret_cast<__half(*)[72]>(sm + ATT_VHI);
    __half (*Vlo)[72] = reinterpret_cast<__half(*)[72]>(sm + ATT_VLO);
    float  (*Ss )[72] = reinterpret_cast<float (*)[72]>(sm + ATT_SS);
    __half (*Phi)[72] = reinterpret_cast<__half(*)[72]>(sm + ATT_PHI);
    __half (*Plo)[72] = reinterpret_cast<__half(*)[72]>(sm + ATT_PLO);
    float  (*Zs )[72] = reinterpret_cast<float (*)[72]>(sm + ATT_ZS);
    float* ms = reinterpret_cast<float*>(sm + ATT_MS);
    float* ls = reinterpret_cast<float*>(sm + ATT_LS);

    const int qt = blockIdx.x, n = blockIdx.y, b = blockIdx.z;
    const int tid = threadIdx.x, warp = tid >> 5;
    const int qbase = qt * 64;
    const int r0  = (warp >> 1) * 16;   // 4 warps over 64 rows
    const int c0w = (warp & 1) * 32;    // 2 warps over 64 cols

    // load Q tile (hi+lo): 64x64, 512 uint4 per array
#pragma unroll
    for (int t = 0; t < 2; t++) {
        int idx = tid + t * 256;
        int r = idx >> 3, c8 = (idx & 7) * 8;
        size_t gi = (((size_t)b * SQ + qbase + r) * NH + n) * H + c8;
        *(uint4*)&Qhi[r][c8] = *(const uint4*)&g_qh_hi[gi];
        *(uint4*)&Qlo[r][c8] = *(const uint4*)&g_qh_lo[gi];
    }
    for (int idx = tid; idx < 64 * 72; idx += 256) (&Zs[0][0])[idx] = 0.0f;
    if (tid < 64) { ms[tid] = -1e30f; ls[tid] = 0.0f; }
    __syncthreads();

    for (int j = 0; j <= qt; j++) {
        const int kbase = j * 64;
#pragma unroll
        for (int t = 0; t < 2; t++) {
            int idx = tid + t * 256;
            int r = idx >> 3, c8 = (idx & 7) * 8;
            size_t gi = (((size_t)b * SK + kbase + r) * NH + n) * H + c8;
            *(uint4*)&Khi[r][c8] = *(const uint4*)&g_kh_hi[gi];
            *(uint4*)&Klo[r][c8] = *(const uint4*)&g_kh_lo[gi];
            *(uint4*)&Vhi[r][c8] = *(const uint4*)&g_vh_hi[gi];
            *(uint4*)&Vlo[r][c8] = *(const uint4*)&g_vh_lo[gi];
        }
        __syncthreads();

        // S = Q @ K^T  (warp: 16x32 slice)
        wmma::fragment<wmma::accumulator, 16, 16, 16, float> sacc[2];
#pragma unroll
        for (int nf = 0; nf < 2; nf++) wmma::fill_fragment(sacc[nf], 0.0f);
#pragma unroll
        for (int ks = 0; ks < 4; ks++) {
            wmma::fragment<wmma::matrix_a, 16, 16, 16, __half, wmma::row_major> qhi, qlo;
            wmma::load_matrix_sync(qhi, &Qhi[r0][ks * 16], 72);
            wmma::load_matrix_sync(qlo, &Qlo[r0][ks * 16], 72);
#pragma unroll
            for (int nf = 0; nf < 2; nf++) {
                wmma::fragment<wmma::matrix_b, 16, 16, 16, __half, wmma::col_major> bf;
                wmma::load_matrix_sync(bf, &Khi[c0w + nf * 16][ks * 16], 72);
                wmma::mma_sync(sacc[nf], qhi, bf, sacc[nf]);
                wmma::mma_sync(sacc[nf], qlo, bf, sacc[nf]);
                wmma::load_matrix_sync(bf, &Klo[c0w + nf * 16][ks * 16], 72);
                wmma::mma_sync(sacc[nf], qhi, bf, sacc[nf]);
            }
        }
#pragma unroll
        for (int nf = 0; nf < 2; nf++)
            wmma::store_matrix_sync(&Ss[r0][c0w + nf * 16], sacc[nf], 72, wmma::mem_row_major);
        __syncthreads();

        // online softmax: 4 threads/row, 16 cols each
        {
            const int row = tid >> 2;
            const int c0  = (tid & 2) ? (tid & 1) * 16 + 32 : (tid & 1) * 16;  // 0,16,32,48
            const int qidx = qbase + row;
            const bool diag = (j == qt);
            float vals[16];
            float mx = -1e30f;
#pragma unroll
            for (int c = 0; c < 16; c++) {
                float s = Ss[row][c0 + c];
                if (diag && (kbase + c0 + c > qidx)) s = -1e30f;
                vals[c] = s;
                mx = fmaxf(mx, s);
            }
            mx = fmaxf(mx, __shfl_xor_sync(0xffffffffu, mx, 1));
            mx = fmaxf(mx, __shfl_xor_sync(0xffffffffu, mx, 2));
            float mold = ms[row];
            float mnew = fmaxf(mold, mx);
            float sum = 0.0f;
#pragma unroll
            for (int c = 0; c < 16; c++) {
                float p = (vals[c] > -1e29f) ? __expf(vals[c] - mnew) : 0.0f;
                split2(p, Phi[row][c0 + c], Plo[row][c0 + c]);
                sum += p;
            }
            sum += __shfl_xor_sync(0xffffffffu, sum, 1);
            sum += __shfl_xor_sync(0xffffffffu, sum, 2);
            float alpha = __expf(mold - mnew);
            if ((tid & 3) == 0) {
                ms[row] = mnew;
                ls[row] = ls[row] * alpha + sum;
            }
#pragma unroll
            for (int c = 0; c < 16; c++) Zs[row][c0 + c] *= alpha;
        }
        __syncthreads();

        // Z += P @ V  (warp: 16x32 slice)
        wmma::fragment<wmma::accumulator, 16, 16, 16, float> zacc[2];
#pragma unroll
        for (int nf = 0; nf < 2; nf++)
            wmma::load_matrix_sync(zacc[nf], &Zs[r0][c0w + nf * 16], 72, wmma::mem_row_major);
#pragma unroll
        for (int ks = 0; ks < 4; ks++) {
            wmma::fragment<wmma::matrix_a, 16, 16, 16, __half, wmma::row_major> phi, plo;
            wmma::load_matrix_sync(phi, &Phi[r0][ks * 16], 72);
            wmma::load_matrix_sync(plo, &Plo[r0][ks * 16], 72);
#pragma unroll
            for (int nf = 0; nf < 2; nf++) {
                wmma::fragment<wmma::matrix_b, 16, 16, 16, __half, wmma::row_major> bf;
                wmma::load_matrix_sync(bf, &Vhi[ks * 16][c0w + nf * 16], 72);
                wmma::mma_sync(zacc[nf], phi, bf, zacc[nf]);
                wmma::mma_sync(zacc[nf], plo, bf, zacc[nf]);
                wmma::load_matrix_sync(bf, &Vlo[ks * 16][c0w + nf * 16], 72);
                wmma::mma_sync(zacc[nf], phi, bf, zacc[nf]);
            }
        }
#pragma unroll
        for (int nf = 0; nf < 2; nf++)
            wmma::store_matrix_sync(&Zs[r0][c0w + nf * 16], zacc[nf], 72, wmma::mem_row_major);
        __syncthreads();
    }

    // finalize: z = Z / l -> hi/lo
    {
        const int row = tid >> 2;
        const int c0  = (tid & 3) * 16;
        float inv = 1.0f / ls[row];
#pragma unroll
        for (int c = 0; c < 16; c++) {
            float z = Zs[row][c0 + c] * inv;
            size_t gi = (((size_t)b * SQ + qbase + row) * NH + n) * H + c0 + c;
            split2(z, g_zh_hi[gi], g_zh_lo[gi]);
        }
    }
}

// ---------------- launch ----------------
extern "C" void kernel_launch(void* const* d_in, const int* in_sizes, int n_in,
                              void* d_out, int out_size) {
    const float* x_q   = (const float*)d_in[0];
    const float* x_kv  = (const float*)d_in[1];
    const float* W_Q   = (const float*)d_in[3];
    const float* W_K   = (const float*)d_in[4];
    const float* W_V   = (const float*)d_in[5];
    const float* W_O   = (const float*)d_in[6];
    const float* b_Q   = (const float*)d_in[7];
    const float* b_K   = (const float*)d_in[8];
    const float* b_V   = (const float*)d_in[9];
    const float* b_O   = (const float*)d_in[10];
    const float* ln1_g = (const float*)d_in[11];
    const float* ln1_b = (const float*)d_in[12];
    const float* ln2_g = (const float*)d_in[13];
    const float* ln2_b = (const float*)d_in[14];

    float* out_f = (float*)d_out;
    float* k_out = nullptr;
    float* v_out = nullptr;
    if (out_size >= 3 * M * D) {
        k_out = out_f + (size_t)M * D;
        v_out = out_f + (size_t)2 * M * D;
    }

    cudaFuncSetAttribute(k_gemm<0>, cudaFuncAttributeMaxDynamicSharedMemorySize, GEMM_SMEM);
    cudaFuncSetAttribute(k_gemm<1>, cudaFuncAttributeMaxDynamicSharedMemorySize, GEMM_SMEM);
    cudaFuncSetAttribute(k_gemm<2>, cudaFuncAttributeMaxDynamicSharedMemorySize, GEMM_SMEM);
    cudaFuncSetAttribute(k_gemm<3>, cudaFuncAttributeMaxDynamicSharedMemorySize, GEMM_SMEM);
    cudaFuncSetAttribute(k_attn,    cudaFuncAttributeMaxDynamicSharedMemorySize, ATT_SMEM);

    const int TPB = 256;
    k_convert_x<<<(M * D + TPB - 1) / TPB, TPB>>>(x_q, x_kv);
    k_convert_w<<<(D * D + TPB - 1) / TPB, TPB>>>(W_Q, W_K, W_V, W_O);

    dim3 ggrid(D / BN, M / BM);   // (8, 32)
    k_gemm<0><<<ggrid, 256, GEMM_SMEM>>>(b_Q, nullptr);
    k_gemm<1><<<ggrid, 256, GEMM_SMEM>>>(b_K, nullptr);
    k_gemm<2><<<ggrid, 256, GEMM_SMEM>>>(b_V, v_out);

    k_ln<0><<<(M * NH) / 8, 256>>>(ln1_g, ln1_b, nullptr);
    k_ln<1><<<(M * NH) / 8, 256>>>(ln2_g, ln2_b, k_out);

    dim3 agrid(SQ / 64, NH, B);   // (32, 16, 2)
    k_attn<<<agrid, 256, ATT_SMEM>>>();

    k_gemm<3><<<ggrid, 256, GEMM_SMEM>>>(b_O, out_f);
}